// round 12
// baseline (speedup 1.0000x reference)
#include <cuda_runtime.h>

#define BB 512
#define SS 1024
#define TT 48
#define MID 512
#define LN64 4.1588830833596715f

typedef unsigned long long u64;

__device__ float g_nll[BB];
__device__ float g_alpha[BB][TT];   // E^T alpha_512 (transition-applied, renormed)
__device__ float g_beta[BB][TT];    // v_513 = pe_513 ⊙ beta_513
__device__ float g_cA[BB], g_cB[BB];

__device__ __forceinline__ u64 ffma2(u64 a, u64 b, u64 c) {
    u64 d; asm("fma.rn.f32x2 %0, %1, %2, %3;" : "=l"(d) : "l"(a), "l"(b), "l"(c)); return d;
}
__device__ __forceinline__ u64 fmul2(u64 a, u64 b) {
    u64 d; asm("mul.rn.f32x2 %0, %1, %2;" : "=l"(d) : "l"(a), "l"(b)); return d;
}
__device__ __forceinline__ u64 fadd2(u64 a, u64 b) {
    u64 d; asm("add.rn.f32x2 %0, %1, %2;" : "=l"(d) : "l"(a), "l"(b)); return d;
}
__device__ __forceinline__ u64 pack2(float lo, float hi) {
    u64 d; asm("mov.b64 %0, {%1, %2};" : "=l"(d) : "f"(lo), "f"(hi)); return d;
}
__device__ __forceinline__ void unpack2(u64 v, float& lo, float& hi) {
    asm("mov.b64 {%0, %1}, %2;" : "=f"(lo), "=f"(hi) : "l"(v));
}

// ---------------------------------------------------------------------------
// DUAL-sequence warp-per-2-batches bidirectional scan.
// Blocks [0,256): forward halves of batches (2x, 2x+1).
// Blocks [256,512): backward halves of batches (2(x-256), +1).
// Both sequences in a warp share the SAME E coefficient registers (same
// direction => same matrix orientation). Lanes 0..23 own output pairs
// (2j, 2j+1); lane 24 runs E=ones -> sum(p) for the renorm (every 4 steps,
// lagged apply via shfl). 1/64 folded into E; prob-domain recursion; raw
// emission LDG ring 4 ahead per sequence; exp at consume. Gold in combine.
// ---------------------------------------------------------------------------
__global__ void __launch_bounds__(32) crf_fwdbwd(
    const float* __restrict__ em,       // [B,S,T]
    const float* __restrict__ trans,    // [T,T]
    const float* __restrict__ startt,   // [T]
    const float* __restrict__ endt,     // [T]
    const int* __restrict__ mask)       // [B,S] bool as int32
{
    __shared__ __align__(16) u64 p_sh[2][2][32];   // [buf][seq][lane]

    const int j  = threadIdx.x;
    const int jx = (j < 24) ? j : 23;
    const bool active = (j < 24);
    const bool is_fwd = (blockIdx.x < BB / 2);
    const int bb0 = (is_fwd ? blockIdx.x : (blockIdx.x - BB / 2)) * 2;

    const float inv64 = 0.015625f;
    const int c0 = 2 * jx, c1 = 2 * jx + 1;

    // Shared coefficient registers (48 u64). Lanes >=24: ones (sum lane).
    u64 E2a[24], E2b[24];
#pragma unroll
    for (int u = 0; u < 24; u++) {
        float a0, a1, b0, b1;
        if (is_fwd) {
            a0 = __expf(__ldg(&trans[(2 * u) * TT + c0])) * inv64;
            a1 = __expf(__ldg(&trans[(2 * u + 1) * TT + c0])) * inv64;
            b0 = __expf(__ldg(&trans[(2 * u) * TT + c1])) * inv64;
            b1 = __expf(__ldg(&trans[(2 * u + 1) * TT + c1])) * inv64;
        } else {
            a0 = __expf(__ldg(&trans[c0 * TT + 2 * u])) * inv64;
            a1 = __expf(__ldg(&trans[c0 * TT + 2 * u + 1])) * inv64;
            b0 = __expf(__ldg(&trans[c1 * TT + 2 * u])) * inv64;
            b1 = __expf(__ldg(&trans[c1 * TT + 2 * u + 1])) * inv64;
        }
        if (!active) { a0 = a1 = 1.0f; b0 = b1 = 1.0f; }
        E2a[u] = pack2(a0, a1);
        E2b[u] = pack2(b0, b1);
    }

    const float* emb0 = em + (size_t)bb0 * SS * TT;
    const float* emb1 = em + (size_t)(bb0 + 1) * SS * TT;
    const int* mk0 = mask + (size_t)bb0 * SS;
    const int* mk1 = mask + (size_t)(bb0 + 1) * SS;

    u64 q2[2];
    float r_reg[2] = {1.0f, 1.0f};
    float c_loc[2] = {0.0f, 0.0f};

    float2 ee[2][4];
    int mm[2][4];

    // matvec: 12x LDS.128 (uniform-addr broadcast), 8 accums depth 6
    auto matvec = [&](const u64* pv, float& s0, float& s1) {
        const ulonglong2* pq = (const ulonglong2*)pv;
        u64 aA[4], aB[4];
#pragma unroll
        for (int w = 0; w < 4; w++) {
            ulonglong2 v0 = pq[3 * w];
            ulonglong2 v1 = pq[3 * w + 1];
            ulonglong2 v2 = pq[3 * w + 2];
            const int e0i = 6 * w;
            u64 x = fmul2(v0.x, E2a[e0i]);
            u64 y = fmul2(v0.x, E2b[e0i]);
            x = ffma2(v0.y, E2a[e0i + 1], x);
            y = ffma2(v0.y, E2b[e0i + 1], y);
            x = ffma2(v1.x, E2a[e0i + 2], x);
            y = ffma2(v1.x, E2b[e0i + 2], y);
            x = ffma2(v1.y, E2a[e0i + 3], x);
            y = ffma2(v1.y, E2b[e0i + 3], y);
            x = ffma2(v2.x, E2a[e0i + 4], x);
            y = ffma2(v2.x, E2b[e0i + 4], y);
            x = ffma2(v2.y, E2a[e0i + 5], x);
            y = ffma2(v2.y, E2b[e0i + 5], y);
            aA[w] = x;
            aB[w] = y;
        }
        u64 acc0 = fadd2(fadd2(aA[0], aA[1]), fadd2(aA[2], aA[3]));
        u64 acc1 = fadd2(fadd2(aB[0], aB[1]), fadd2(aB[2], aB[3]));
        float l0, h0, l1, h1;
        unpack2(acc0, l0, h0);
        unpack2(acc1, l1, h1);
        s0 = l0 + h0;                   // lane24: s0 = sum(p)
        s1 = l1 + h1;
    };

    // one dual step; flags compile-time
    auto step = [&](int t, int k, int tn, bool apply_r, bool do_renorm,
                    bool do_pref) {
        const int buf = t & 1;
        p_sh[buf][0][j] = q2[0];
        p_sh[buf][1][j] = q2[1];

        const float2 eA = ee[0][k], eB = ee[1][k];
        const int mA = mm[0][k], mB = mm[1][k];

        __syncwarp();

        if (do_pref) {
            ee[0][k] = *(const float2*)&emb0[(size_t)tn * TT + 2 * jx];
            ee[1][k] = *(const float2*)&emb1[(size_t)tn * TT + 2 * jx];
            mm[0][k] = mk0[tn];
            mm[1][k] = mk1[tn];
        }

        float sA0, sA1, sB0, sB1;
        matvec(&p_sh[buf][0][0], sA0, sA1);
        matvec(&p_sh[buf][1][0], sB0, sB1);

        const u64 qnA = pack2(sA0 * __expf(eA.x), sA1 * __expf(eA.y));
        const u64 qnB = pack2(sB0 * __expf(eB.x), sB1 * __expf(eB.y));
        q2[0] = mA ? qnA : q2[0];
        q2[1] = mB ? qnB : q2[1];

        if (apply_r) {
            const float rA = __shfl_sync(0xffffffffu, r_reg[0], 24);
            const float rB = __shfl_sync(0xffffffffu, r_reg[1], 24);
            q2[0] = fmul2(q2[0], pack2(rA, rA));
            q2[1] = fmul2(q2[1], pack2(rB, rB));
        }
        if (do_renorm) {                // branch-free; only lane24's matters
            r_reg[0] = __fdividef(1.0f, sA0);
            c_loc[0] += __logf(sA0);
            r_reg[1] = __fdividef(1.0f, sB0);
            c_loc[1] += __logf(sB0);
        }
    };

    if (is_fwd) {
        // init alpha_0 = exp(start + e0) for both batches
        q2[0] = pack2(__expf(startt[c0] + emb0[c0]),
                      __expf(startt[c1] + emb0[c1]));
        q2[1] = pack2(__expf(startt[c0] + emb1[c0]),
                      __expf(startt[c1] + emb1[c1]));
#pragma unroll
        for (int k = 0; k < 4; k++) {
            int t = 1 + k;
            ee[0][k] = *(const float2*)&emb0[(size_t)t * TT + 2 * jx];
            ee[1][k] = *(const float2*)&emb1[(size_t)t * TT + 2 * jx];
            mm[0][k] = mk0[t];
            mm[1][k] = mk1[t];
        }
        for (int tb = 0; tb < 128; tb++) {
            const int t0 = 1 + tb * 4;
#pragma unroll
            for (int k = 0; k < 4; k++) {
                int t = t0 + k;
                int tn = t + 4; tn = (tn < MID + 1) ? tn : MID;
                step(t, k, tn, k == 0, k == 3, true);
            }
        }
        // a = E^T alpha_512 per batch, pending renorm applied
        {
            const int buf = 513 & 1;
            p_sh[buf][0][j] = q2[0];
            p_sh[buf][1][j] = q2[1];
            __syncwarp();
            float sA0, sA1, sB0, sB1;
            matvec(&p_sh[buf][0][0], sA0, sA1);
            matvec(&p_sh[buf][1][0], sB0, sB1);
            const float rA = __shfl_sync(0xffffffffu, r_reg[0], 24);
            const float rB = __shfl_sync(0xffffffffu, r_reg[1], 24);
            if (active) {
                *(float2*)&g_alpha[bb0][2 * j]     = make_float2(sA0 * rA, sA1 * rA);
                *(float2*)&g_alpha[bb0 + 1][2 * j] = make_float2(sB0 * rB, sB1 * rB);
            }
        }
        const float cA0 = __shfl_sync(0xffffffffu, c_loc[0], 24);
        const float cA1 = __shfl_sync(0xffffffffu, c_loc[1], 24);
        if (j == 0) { g_cA[bb0] = cA0; g_cA[bb0 + 1] = cA1; }
    } else {
        // init v_1023 = exp(e_1023 + end)
        const float* eL0 = &emb0[(size_t)(SS - 1) * TT];
        const float* eL1 = &emb1[(size_t)(SS - 1) * TT];
        q2[0] = pack2(__expf(eL0[c0] + endt[c0]), __expf(eL0[c1] + endt[c1]));
        q2[1] = pack2(__expf(eL1[c0] + endt[c0]), __expf(eL1[c1] + endt[c1]));
#pragma unroll
        for (int k = 0; k < 4; k++) {
            int t = SS - 2 - k;
            ee[0][k] = *(const float2*)&emb0[(size_t)t * TT + 2 * jx];
            ee[1][k] = *(const float2*)&emb1[(size_t)t * TT + 2 * jx];
            mm[0][k] = mk0[t];
            mm[1][k] = mk1[t];
        }
        // 510 steps: 127 blocks of 4 (s=0..507), then 2 peel (s=508,509)
        for (int sb = 0; sb < 127; sb++) {
            const int s0i = sb * 4;
#pragma unroll
            for (int k = 0; k < 4; k++) {
                int s = s0i + k;
                int t = SS - 2 - s;
                int tn = t - 4; tn = (tn > MID) ? tn : (MID + 1);
                step(t, k, tn, k == 0, k == 3, true);
            }
        }
        step(514, 0, MID + 1, true, false, false);   // s=508
        step(513, 1, MID + 1, false, false, false);  // s=509
        if (active) {
            float l0, h0, l1, h1;
            unpack2(q2[0], l0, h0);
            unpack2(q2[1], l1, h1);
            *(float2*)&g_beta[bb0][2 * j]     = make_float2(l0, h0);
            *(float2*)&g_beta[bb0 + 1][2 * j] = make_float2(l1, h1);
        }
        const float cB0 = __shfl_sync(0xffffffffu, c_loc[0], 24);
        const float cB1 = __shfl_sync(0xffffffffu, c_loc[1], 24);
        if (j == 0) { g_cB[bb0] = cB0; g_cB[bb0 + 1] = cB1; }
    }
}

// ---------------------------------------------------------------------------
// Combine: gold path + mask counts (parallel over t) + alpha·beta dot + final.
// ---------------------------------------------------------------------------
__global__ void __launch_bounds__(128) crf_combine(
    const float* __restrict__ em,
    const float* __restrict__ trans,
    const float* __restrict__ startt,
    const float* __restrict__ endt,
    const int* __restrict__ tags,
    const int* __restrict__ mask)
{
    __shared__ float rg[128];
    __shared__ int   rc[128], ra[128], rb[128];
    __shared__ float dot[TT];

    const int b = blockIdx.x;
    const int tid = threadIdx.x;
    const int* tg = tags + (size_t)b * SS;
    const int* mk = mask + (size_t)b * SS;
    const float* emb = em + (size_t)b * SS * TT;

    if (tid < TT) dot[tid] = g_alpha[b][tid] * g_beta[b][tid];

    float g = 0.0f;
    int cnt = 0, nA = 0, nB = 0;
    for (int t = tid; t < SS; t += 128) {
        const int mt = mk[t] ? 1 : 0;
        cnt += mt;
        if (t == 0) {
            g += startt[tg[0]] + emb[tg[0]];
        } else if (mt) {
            g += trans[tg[t - 1] * TT + tg[t]] + emb[(size_t)t * TT + tg[t]];
            if (t <= MID) nA++; else if (t <= SS - 2) nB++;
        }
    }
    rg[tid] = g; rc[tid] = cnt; ra[tid] = nA; rb[tid] = nB;
    __syncthreads();
    for (int off = 64; off > 0; off >>= 1) {
        if (tid < off) {
            rg[tid] += rg[tid + off];
            rc[tid] += rc[tid + off];
            ra[tid] += ra[tid + off];
            rb[tid] += rb[tid + off];
        }
        __syncthreads();
    }
    if (tid == 0) {
        float s = 0.0f;
#pragma unroll
        for (int i = 0; i < TT; i++) s += dot[i];
        // applied matvecs: nA masked (t=1..512) + 1 transition-only + nB (t=513..1022)
        const float logZ = g_cA[b] + g_cB[b]
                         + (float)(ra[0] + 1 + rb[0]) * LN64 + __logf(s);
        const int len = rc[0] - 1;
        const float gold = rg[0] + endt[tg[len]];
        g_nll[b] = logZ - gold;
    }
}

// ---------------------------------------------------------------------------
__global__ void __launch_bounds__(512) crf_reduce(float* __restrict__ out)
{
    __shared__ float rs[512];
    const int tid = threadIdx.x;
    rs[tid] = g_nll[tid];
    __syncthreads();
    for (int off = 256; off > 0; off >>= 1) {
        if (tid < off) rs[tid] += rs[tid + off];
        __syncthreads();
    }
    if (tid == 0) out[0] = rs[0] / (float)BB;
}

extern "C" void kernel_launch(void* const* d_in, const int* in_sizes, int n_in,
                              void* d_out, int out_size)
{
    const float* em   = (const float*)d_in[0];
    const float* tr   = (const float*)d_in[1];
    const float* st   = (const float*)d_in[2];
    const float* en   = (const float*)d_in[3];
    const int*   tags = (const int*)d_in[4];
    const int*   mask = (const int*)d_in[5];
    float* out = (float*)d_out;

    crf_fwdbwd<<<BB, 32>>>(em, tr, st, en, mask);
    crf_combine<<<BB, 128>>>(em, tr, st, en, tags, mask);
    crf_reduce<<<1, 512>>>(out);
}

// round 13
// speedup vs baseline: 1.2806x; 1.2806x over previous
#include <cuda_runtime.h>

#define BB 512
#define SS 1024
#define TT 48
#define MID 512
#define LN64 4.1588830833596715f

typedef unsigned long long u64;

__device__ float g_nll[BB];
__device__ float g_alpha[BB][TT];   // E^T alpha_512 (transition-applied, renormed)
__device__ float g_beta[BB][TT];    // v_513 = pe_513 ⊙ beta_513
__device__ float g_cA[BB], g_cB[BB];

__device__ __forceinline__ u64 ffma2(u64 a, u64 b, u64 c) {
    u64 d; asm("fma.rn.f32x2 %0, %1, %2, %3;" : "=l"(d) : "l"(a), "l"(b), "l"(c)); return d;
}
__device__ __forceinline__ u64 fmul2(u64 a, u64 b) {
    u64 d; asm("mul.rn.f32x2 %0, %1, %2;" : "=l"(d) : "l"(a), "l"(b)); return d;
}
__device__ __forceinline__ u64 fadd2(u64 a, u64 b) {
    u64 d; asm("add.rn.f32x2 %0, %1, %2;" : "=l"(d) : "l"(a), "l"(b)); return d;
}
__device__ __forceinline__ u64 pack2(float lo, float hi) {
    u64 d; asm("mov.b64 %0, {%1, %2};" : "=l"(d) : "f"(lo), "f"(hi)); return d;
}
__device__ __forceinline__ void unpack2(u64 v, float& lo, float& hi) {
    asm("mov.b64 {%0, %1}, %2;" : "=f"(lo), "=f"(hi) : "l"(v));
}

// ---------------------------------------------------------------------------
// Bidirectional scan, TWO warps per sequence-half (64-thread blocks, 1024
// blocks -> 2048 warps). Warp w's lanes 0..23 each own ONE output state
// o = 24*w + lane: 24 ffma2 per lane per step (f32x2 over input pairs),
// coefficients in 48 regs. q is a scalar float per lane, broadcast through
// a 48-float shared buffer (double-buffered). Thread 24 of warp 0 runs
// E=ones -> sum(p); renorm every 8 steps, lagged apply via shared r_sh
// (write at k==7, read after the k==0 barrier). 1/64 folded into E.
// Emission LDG ring 8 ahead (raw); exp at consume. Gold in combine kernel.
// ---------------------------------------------------------------------------
__global__ void __launch_bounds__(64) crf_fwdbwd(
    const float* __restrict__ em,       // [B,S,T]
    const float* __restrict__ trans,    // [T,T]
    const float* __restrict__ startt,   // [T]
    const float* __restrict__ endt,     // [T]
    const int* __restrict__ mask)       // [B,S] bool as int32
{
    __shared__ __align__(16) float q_sh[2][TT];
    __shared__ float r_sh;

    const int tid  = threadIdx.x;
    const int wid  = tid >> 5;
    const int lane = tid & 31;
    const bool active = (lane < 24);
    const bool is_sum = (tid == 24);    // warp0 lane24
    const int o  = active ? (wid * 24 + lane) : 0;   // owned output state
    const bool is_fwd = (blockIdx.x < BB);
    const int b = is_fwd ? blockIdx.x : (blockIdx.x - BB);

    const float inv64 = 0.015625f;

    // 24 packed coefficient pairs (48 regs). Sum lane: ones (no inv64).
    u64 E2[24];
#pragma unroll
    for (int u = 0; u < 24; u++) {
        float a, bb;
        if (is_fwd) {
            a  = __expf(__ldg(&trans[(2 * u) * TT + o])) * inv64;
            bb = __expf(__ldg(&trans[(2 * u + 1) * TT + o])) * inv64;
        } else {
            a  = __expf(__ldg(&trans[o * TT + 2 * u])) * inv64;
            bb = __expf(__ldg(&trans[o * TT + 2 * u + 1])) * inv64;
        }
        if (is_sum) { a = 1.0f; bb = 1.0f; }
        E2[u] = pack2(a, bb);
    }

    const float* emb = em + (size_t)b * SS * TT;
    const int* mk = mask + (size_t)b * SS;

    float q;                            // scalar state (sum lane: junk)
    float c_loc = 0.0f;

    float ee[8];
    int mm[8];

    if (tid == 0) r_sh = 1.0f;

    // matvec: 12x LDS.128 broadcast, 4 accums x 6 fma2, horizontal sum
    auto matvec = [&](int buf) -> float {
        const ulonglong2* pq = (const ulonglong2*)q_sh[buf];
        u64 acc[4];
#pragma unroll
        for (int w = 0; w < 4; w++) {
            ulonglong2 v0 = pq[3 * w];
            ulonglong2 v1 = pq[3 * w + 1];
            ulonglong2 v2 = pq[3 * w + 2];
            const int e0 = 6 * w;
            u64 x = fmul2(v0.x, E2[e0]);
            x = ffma2(v0.y, E2[e0 + 1], x);
            x = ffma2(v1.x, E2[e0 + 2], x);
            x = ffma2(v1.y, E2[e0 + 3], x);
            x = ffma2(v2.x, E2[e0 + 4], x);
            x = ffma2(v2.y, E2[e0 + 5], x);
            acc[w] = x;
        }
        u64 a2 = fadd2(fadd2(acc[0], acc[1]), fadd2(acc[2], acc[3]));
        float lo, hi;
        unpack2(a2, lo, hi);
        return lo + hi;                 // sum lane: sum(p)
    };

    // one step; flags compile-time
    auto step = [&](int t, int k, int tn, bool apply_r, bool do_renorm,
                    bool do_pref) {
        const int buf = t & 1;
        if (active) q_sh[buf][o] = q;

        const float e_k = ee[k];
        const int   m_k = mm[k];

        __syncthreads();

        if (do_pref) {
            ee[k] = emb[(size_t)tn * TT + o];
            mm[k] = mk[tn];
        }

        const float s = matvec(buf);

        const float qn = s * __expf(e_k);
        q = m_k ? qn : q;

        if (apply_r) q *= r_sh;         // lagged renorm (sync above orders it)
        if (do_renorm && is_sum) {      // single thread, once per 8 steps
            r_sh = __fdividef(1.0f, s);
            c_loc += __logf(s);
        }
    };

    if (is_fwd) {
        q = __expf(startt[o] + emb[o]);
#pragma unroll
        for (int k = 0; k < 8; k++) {
            int t = 1 + k;
            ee[k] = emb[(size_t)t * TT + o];
            mm[k] = mk[t];
        }
        __syncthreads();                // r_sh init visible
        for (int tb = 0; tb < 64; tb++) {
            const int t0 = 1 + tb * 8;
#pragma unroll
            for (int k = 0; k < 8; k++) {
                int t = t0 + k;
                int tn = t + 8; tn = (tn < MID + 1) ? tn : MID;
                step(t, k, tn, k == 0, k == 7, true);
            }
        }
        // a = E^T alpha_512 with pending renorm applied
        {
            const int buf = 513 & 1;
            if (active) q_sh[buf][o] = q;
            __syncthreads();
            const float s = matvec(buf);
            if (active) g_alpha[b][o] = s * r_sh;
        }
        if (is_sum) g_cA[b] = c_loc;
    } else {
        const float* eL = &emb[(size_t)(SS - 1) * TT];
        q = __expf(eL[o] + endt[o]);
#pragma unroll
        for (int k = 0; k < 8; k++) {
            int t = SS - 2 - k;
            ee[k] = emb[(size_t)t * TT + o];
            mm[k] = mk[t];
        }
        __syncthreads();                // r_sh init visible
        // 510 steps: 63 blocks of 8 (t=1022..519), then 6 peel (t=518..513)
        for (int sb = 0; sb < 63; sb++) {
            const int s0i = sb * 8;
#pragma unroll
            for (int k = 0; k < 8; k++) {
                int s = s0i + k;
                int t = SS - 2 - s;
                int tn = t - 8; tn = (tn > MID + 1) ? tn : (MID + 1);
                step(t, k, tn, k == 0, k == 7, true);
            }
        }
#pragma unroll
        for (int k = 0; k < 6; k++) {
            int t = SS - 2 - (504 + k);          // 518..513
            step(t, k, MID + 1, k == 0, false, false);
        }
        if (active) g_beta[b][o] = q;
        if (is_sum) g_cB[b] = c_loc;
    }
}

// ---------------------------------------------------------------------------
// Combine: gold path + mask counts (parallel over t) + alpha·beta dot + final.
// ---------------------------------------------------------------------------
__global__ void __launch_bounds__(128) crf_combine(
    const float* __restrict__ em,
    const float* __restrict__ trans,
    const float* __restrict__ startt,
    const float* __restrict__ endt,
    const int* __restrict__ tags,
    const int* __restrict__ mask)
{
    __shared__ float rg[128];
    __shared__ int   rc[128], ra[128], rb[128];
    __shared__ float dot[TT];

    const int b = blockIdx.x;
    const int tid = threadIdx.x;
    const int* tg = tags + (size_t)b * SS;
    const int* mk = mask + (size_t)b * SS;
    const float* emb = em + (size_t)b * SS * TT;

    if (tid < TT) dot[tid] = g_alpha[b][tid] * g_beta[b][tid];

    float g = 0.0f;
    int cnt = 0, nA = 0, nB = 0;
    for (int t = tid; t < SS; t += 128) {
        const int mt = mk[t] ? 1 : 0;
        cnt += mt;
        if (t == 0) {
            g += startt[tg[0]] + emb[tg[0]];
        } else if (mt) {
            g += trans[tg[t - 1] * TT + tg[t]] + emb[(size_t)t * TT + tg[t]];
            if (t <= MID) nA++; else if (t <= SS - 2) nB++;
        }
    }
    rg[tid] = g; rc[tid] = cnt; ra[tid] = nA; rb[tid] = nB;
    __syncthreads();
    for (int off = 64; off > 0; off >>= 1) {
        if (tid < off) {
            rg[tid] += rg[tid + off];
            rc[tid] += rc[tid + off];
            ra[tid] += ra[tid + off];
            rb[tid] += rb[tid + off];
        }
        __syncthreads();
    }
    if (tid == 0) {
        float s = 0.0f;
#pragma unroll
        for (int i = 0; i < TT; i++) s += dot[i];
        // applied matvecs: nA masked (t=1..512) + 1 transition-only + nB (t=513..1022)
        const float logZ = g_cA[b] + g_cB[b]
                         + (float)(ra[0] + 1 + rb[0]) * LN64 + __logf(s);
        const int len = rc[0] - 1;
        const float gold = rg[0] + endt[tg[len]];
        g_nll[b] = logZ - gold;
    }
}

// ---------------------------------------------------------------------------
__global__ void __launch_bounds__(512) crf_reduce(float* __restrict__ out)
{
    __shared__ float rs[512];
    const int tid = threadIdx.x;
    rs[tid] = g_nll[tid];
    __syncthreads();
    for (int off = 256; off > 0; off >>= 1) {
        if (tid < off) rs[tid] += rs[tid + off];
        __syncthreads();
    }
    if (tid == 0) out[0] = rs[0] / (float)BB;
}

extern "C" void kernel_launch(void* const* d_in, const int* in_sizes, int n_in,
                              void* d_out, int out_size)
{
    const float* em   = (const float*)d_in[0];
    const float* tr   = (const float*)d_in[1];
    const float* st   = (const float*)d_in[2];
    const float* en   = (const float*)d_in[3];
    const int*   tags = (const int*)d_in[4];
    const int*   mask = (const int*)d_in[5];
    float* out = (float*)d_out;

    crf_fwdbwd<<<2 * BB, 64>>>(em, tr, st, en, mask);
    crf_combine<<<BB, 128>>>(em, tr, st, en, tags, mask);
    crf_reduce<<<1, 512>>>(out);
}